// round 10
// baseline (speedup 1.0000x reference)
#include <cuda_runtime.h>

#define NBOX 16384
#define NW   256            // 64-bit words per mask row
#define NBKT 16384          // conf buckets for counting sort
#define NBLK 128            // persistent fixpoint CTAs (must be <= SM count)
#define CONF_THRESH 0.5f
#define PIOU_THRESH 0.5f

typedef unsigned long long u64;

// ---------------- device scratch (static; no allocation) ----------------
__device__ float4 g_seph[NBOX];                    // sorted [start,end,peak,height]
__device__ float  g_conf[NBOX];                    // dense confidence (unsorted)
__device__ int    g_hist[NBKT];                    // bucket histogram
__device__ int    g_off[NBKT];                     // #elements in buckets > b
__device__ int    g_cnt[NBKT];                     // scatter cursors
__device__ int    g_blist[NBOX];                   // bucket-grouped original indices
__device__ int    g_M;                             // count(conf > 0.5) == valid prefix len
__device__ u64    g_mask[(size_t)NBOX * NW];       // 32MB suppression bitmask
__device__ u64    g_D[NW];                         // definitely-kept bitmap (grows)
__device__ u64    g_suppD[NW];                     // accumulated suppr(D)
__device__ int    g_ulist[2][NBOX];                // undecided rows (double buffer)
__device__ int    g_dlist[2][NBOX];                // newly-kept rows (double buffer)
__device__ int    g_un[2], g_dn[2];                // list counters
__device__ int    g_bar_count;                     // grid barrier ticket
__device__ int    g_bar_gen;                       // grid barrier generation
__device__ int    g_diff;                          // convergence flag (epoch-tagged)

__device__ __forceinline__ int bucket_of(float c) {
    int b = (int)(c * 16384.0f);                   // exact pow2 mul; monotone
    return b > 16383 ? 16383 : b;
}

// ---------------- 1) gather conf, zero accumulators ----------------
__global__ void k_prep(const float* __restrict__ in) {
    int i = blockIdx.x * blockDim.x + threadIdx.x;
    if (i < NBOX) {
        g_conf[i] = in[i * 5 + 0];
        g_hist[i] = 0;
        g_cnt[i]  = 0;
    }
    if (i == 0) g_M = 0;
}

// ---------------- 2a) bucket histogram ----------------
__global__ void k_hist() {
    int i = blockIdx.x * blockDim.x + threadIdx.x;
    if (i < NBOX) atomicAdd(&g_hist[bucket_of(g_conf[i])], 1);
}

// ---------------- 2b) suffix sums: off[b] = #elements with bucket > b ----------
__global__ void k_suffix() {                       // 1 block, 1024 threads
    __shared__ int part[1024];
    int t = threadIdx.x;
    int base = t * 16;
    int v[16]; int s = 0;
#pragma unroll
    for (int k = 0; k < 16; k++) { v[k] = g_hist[base + k]; s += v[k]; }
    part[t] = s;
    __syncthreads();
    for (int off = 1; off < 1024; off <<= 1) {     // inclusive suffix scan of partials
        int x = (t + off < 1024) ? part[t + off] : 0;
        __syncthreads();
        part[t] += x;
        __syncthreads();
    }
    int above = part[t] - s;                       // sum of buckets >= (t+1)*16
    int o[16];
    o[15] = above;
#pragma unroll
    for (int k = 14; k >= 0; k--) o[k] = o[k + 1] + v[k + 1];
#pragma unroll
    for (int k = 0; k < 16; k++) g_off[base + k] = o[k];
}

// ---------------- 2c) scatter indices into bucket segments ----------------
__global__ void k_bscatter() {
    int i = blockIdx.x * blockDim.x + threadIdx.x;
    if (i >= NBOX) return;
    int b = bucket_of(g_conf[i]);
    int pos = g_off[b] + atomicAdd(&g_cnt[b], 1);
    g_blist[pos] = i;
}

// ---------------- 3) exact rank within bucket + scatter boxes ----------------
__global__ void k_rankscatter(const float* __restrict__ in) {
    int i = blockIdx.x * blockDim.x + threadIdx.x;
    if (i >= NBOX) return;
    float ci = g_conf[i];
    int b    = bucket_of(ci);
    int base = g_off[b], len = g_hist[b];
    int cnt = 0;
    for (int p = base; p < base + len; p++) {
        int j = g_blist[p];
        float cj = g_conf[j];
        cnt += (cj > ci) || (cj == ci && j < i);   // stable: (conf desc, idx asc)
    }
    int r = base + cnt;
    const float* row = in + (size_t)i * 5;
    g_seph[r] = make_float4(row[1], row[2], row[3], row[4]);
    if (ci > CONF_THRESH) atomicAdd(&g_M, 1);
}

// ---------------- 4) pairwise peak-IoU bitmask, upper-triangular blocks only ----
__global__ void k_mask() {
    __shared__ float4 cols[64];
    if (blockIdx.x < blockIdx.y) return;           // triangular: halves the work
    int M = g_M;
    if ((int)(blockIdx.y * 64) >= M) return;
    int j0 = blockIdx.x * 64;
    if (j0 >= M) return;
    int r = blockIdx.y * 64 + threadIdx.x;
    cols[threadIdx.x] = g_seph[j0 + threadIdx.x];
    __syncthreads();
    if (r >= M) return;
    float4 a = g_seph[r];
    float area1 = __fmul_rn(__fsub_rn(a.y, a.x), a.w);
    u64 w = 0;
#pragma unroll 4
    for (int k = 0; k < 64; k++) {
        float4 b = cols[k];
        float is = fmaxf(a.x, b.x);
        float ie = fminf(a.y, b.y);
        float il = __fsub_rn(ie, is);
        bool sup = false;
        if (il > 0.0f) {                           // piou>0 requires overlap
            float inter_h    = fminf(a.w, b.w);
            float inter_area = __fmul_rn(il, inter_h);
            float area2      = __fmul_rn(__fsub_rn(b.y, b.x), b.w);
            float union_area = __fsub_rn(__fadd_rn(area1, area2), inter_area);
            float iou        = __fdiv_rn(inter_area, union_area);
            float pd         = fabsf(__fsub_rn(a.z, b.z));
            float us         = fminf(a.x, b.x);
            float ue         = fmaxf(a.y, b.y);
            float ud         = fabsf(__fsub_rn(ue, us));
            float val        = __fsub_rn(iou, __fdiv_rn(pd, ud));
            sup = (val > PIOU_THRESH);
        }
        w |= ((u64)sup) << k;
    }
    int lim = M - j0;                              // mask invalid cols once
    if (lim < 64) w &= (1ULL << lim) - 1ULL;
    if (r >= j0 && r < j0 + 64) w &= ~(1ULL << (r - j0));   // self never suppresses
    g_mask[(size_t)r * NW + blockIdx.x] = w;
}

// ---------------- 5) persistent incremental fixpoint NMS ----------------
// Iterates: D' = valid & ~(suppD | suppr(U)),  suppD' = suppD | suppr(D'\D),
//           P' = valid & ~suppD'.  Converged iff P' == D'.
// Identical iterates to the full D/P fixpoint, but each sweep touches only the
// undecided list U (phase A) or the newly-kept list Delta (phase B).

__device__ __forceinline__ void gridsync(int& gen) {
    __syncthreads();
    if (threadIdx.x == 0) {
        __threadfence();                           // publish our writes
        if (atomicAdd(&g_bar_count, 1) == NBLK - 1) {
            g_bar_count = 0;
            __threadfence();
            atomicExch(&g_bar_gen, gen + 1);       // release
        } else {
            while (atomicAdd(&g_bar_gen, 0) <= gen) { }
        }
        gen++;
        __threadfence();                           // acquire
    }
    __syncthreads();
}

__device__ __forceinline__ u64 trim_diag(u64 v, int j, int wtop) {
    if (j >= wtop) {                               // diagonal word: keep bits > bj
        int bj = j & 63;
        v = (bj == 63) ? 0ULL : (v & (~0ULL << (bj + 1)));
    }
    return v;
}

__device__ __forceinline__ u64 block_or(u64 v, u64* s_acc) {
#pragma unroll
    for (int o = 16; o > 0; o >>= 1)
        v |= __shfl_down_sync(0xffffffffu, v, o);
    if ((threadIdx.x & 31) == 0) s_acc[threadIdx.x >> 5] = v;
    __syncthreads();
    u64 r = 0ULL;
    if (threadIdx.x == 0) {
#pragma unroll
        for (int k = 0; k < 8; k++) r |= s_acc[k];
    }
    return r;                                      // valid on thread 0 only
}

__global__ void __launch_bounds__(256, 1) k_fix(float4* __restrict__ out) {
    __shared__ u64 s_acc[8];
    __shared__ int s_cont;
    int tid  = threadIdx.x;
    int bid  = blockIdx.x;
    int gtid = bid * 256 + tid;                    // 0..32767
    int gen = 0;
    if (tid == 0) gen = atomicAdd(&g_bar_gen, 0);  // replay-safe baseline
    int M  = g_M;
    int Mw = (M + 63) >> 6;

    // init
    if (gtid < NW) { g_suppD[gtid] = 0ULL; g_D[gtid] = 0ULL; }
    if (gtid == 0) {
        g_diff = 0;
        g_un[0] = g_un[1] = 0;
        g_dn[0] = g_dn[1] = 0;
    }
    gridsync(gen);

    for (int it = 0;; it++) {
        int e = it & 1;
        // reset next-epoch U counter (written in B_it, read in A_{it+1})
        if (gtid == 0) g_un[e] = 0;
        // ---- Phase A: Dnew = valid & ~(suppD | suppr(U_{it-1})) ----
        for (int w = bid; w < Mw; w += NBLK) {
            int hi   = (w + 1) << 6; if (hi > M) hi = M;
            int wtop = w << 6;
            u64 sup = 0ULL;
            if (it == 0) {                         // U_{-1} = all valid: unconditional
#pragma unroll 4
                for (int j = tid; j < hi; j += 256)
                    sup |= trim_diag(g_mask[(size_t)j * NW + w], j, wtop);
            } else {
                int n = g_un[1 - e];
                const int* ul = g_ulist[1 - e];
#pragma unroll 4
                for (int p = tid; p < n; p += 256) {
                    int j = ul[p];
                    if (j < hi)
                        sup |= trim_diag(g_mask[(size_t)j * NW + w], j, wtop);
                }
            }
            sup = block_or(sup, s_acc);
            if (tid == 0) {
                sup |= g_suppD[w];
                int lim = M - wtop;
                u64 vm = (lim >= 64) ? ~0ULL : ((1ULL << lim) - 1ULL);
                u64 dn  = vm & ~sup;
                u64 add = dn & ~g_D[w];
                g_D[w] = dn;
                int na = __popcll(add);
                if (na) {                          // append Delta rows to dlist[e]
                    int base = atomicAdd(&g_dn[e], na);
                    while (add) {
                        int b = __ffsll((long long)add) - 1;
                        add &= add - 1ULL;
                        g_dlist[e][base++] = wtop + b;
                    }
                }
            }
            __syncthreads();                       // s_acc reuse
        }
        gridsync(gen);                             // S1: D + dlist complete
        // reset next-epoch Delta counter (written in A_{it+1})
        if (gtid == 0) g_dn[1 - e] = 0;
        // ---- Phase B: suppD |= suppr(Delta); P = valid & ~suppD; build U ----
        {
            int n = g_dn[e];
            const int* dl = g_dlist[e];
            for (int w = bid; w < Mw; w += NBLK) {
                int hi   = (w + 1) << 6; if (hi > M) hi = M;
                int wtop = w << 6;
                u64 sup = 0ULL;
#pragma unroll 4
                for (int p = tid; p < n; p += 256) {
                    int j = dl[p];
                    if (j < hi)
                        sup |= trim_diag(g_mask[(size_t)j * NW + w], j, wtop);
                }
                sup = block_or(sup, s_acc);
                if (tid == 0) {
                    u64 sd = g_suppD[w] | sup;
                    g_suppD[w] = sd;
                    int lim = M - wtop;
                    u64 vm = (lim >= 64) ? ~0ULL : ((1ULL << lim) - 1ULL);
                    u64 pn   = vm & ~sd;
                    u64 dcur = g_D[w];
                    if (pn != dcur) atomicMax(&g_diff, it + 1);
                    u64 undec = pn & ~dcur;
                    int nu = __popcll(undec);
                    if (nu) {                      // append undecided rows to ulist[e]
                        int base = atomicAdd(&g_un[e], nu);
                        while (undec) {
                            int b = __ffsll((long long)undec) - 1;
                            undec &= undec - 1ULL;
                            g_ulist[e][base++] = wtop + b;
                        }
                    }
                }
                __syncthreads();
            }
        }
        gridsync(gen);                             // S2: suppD/diff/ulist complete
        if (tid == 0) s_cont = (atomicAdd(&g_diff, 0) > it);
        __syncthreads();
        if (!s_cont) break;
    }

    // ---- output: keep == D (== P at fixpoint) ----
    if (gtid < NBOX) {
        u64 kw = g_D[gtid >> 6];
        float4 v = ((kw >> (gtid & 63)) & 1ULL) ? g_seph[gtid]
                                                : make_float4(0.f, 0.f, 0.f, 0.f);
        out[gtid] = v;
    }
}

extern "C" void kernel_launch(void* const* d_in, const int* in_sizes, int n_in,
                              void* d_out, int out_size) {
    const float* in = (const float*)d_in[0];
    float4* out = (float4*)d_out;
    (void)in_sizes; (void)n_in; (void)out_size;

    k_prep       <<<64, 256>>>(in);
    k_hist       <<<64, 256>>>();
    k_suffix     <<<1, 1024>>>();
    k_bscatter   <<<64, 256>>>();
    k_rankscatter<<<64, 256>>>(in);
    k_mask       <<<dim3(256, 256), 64>>>();
    k_fix        <<<NBLK, 256>>>(out);
}